// round 4
// baseline (speedup 1.0000x reference)
#include <cuda_runtime.h>
#include <cuda_fp16.h>
#include <cstdint>
#include <cstddef>

#define DINLINE __device__ __forceinline__

// ---------------- problem dims ----------------
#define MDIM 32768
#define NDIM 1024
#define KDIM 1024

// ---------------- persistent device scratch ----------------
__device__ double g_wsum_part[256];
__device__ float  g_wmax_part[256];
__device__ float  g_a;      // mean(weight)
__device__ float  g_beta;   // max|weight|
__device__ __half g_wq[(size_t)NDIM * KDIM];   // w_q transposed: [N][K], +-1
__device__ __half g_xq[(size_t)MDIM * KDIM];   // quantized activations [M][K]
__device__ float  g_gamma[MDIM];               // per-row max|x|

// ---------------- helpers ----------------
DINLINE uint32_t s2u(const void* p) {
    uint32_t a;
    asm("{ .reg .u64 t; cvta.to.shared.u64 t, %1; cvt.u32.u64 %0, t; }"
        : "=r"(a) : "l"(p));
    return a;
}
DINLINE void cpa16(uint32_t s, const void* g) {
    asm volatile("cp.async.cg.shared.global [%0], [%1], 16;" :: "r"(s), "l"(g));
}
DINLINE uint32_t sw128(uint32_t off) { return off ^ ((off >> 3) & 0x70); }

DINLINE void ldsm_x4(uint32_t addr, uint32_t& r0, uint32_t& r1, uint32_t& r2, uint32_t& r3) {
    asm volatile("ldmatrix.sync.aligned.m8n8.x4.shared.b16 {%0,%1,%2,%3}, [%4];"
                 : "=r"(r0), "=r"(r1), "=r"(r2), "=r"(r3) : "r"(addr));
}
DINLINE void mma16816(float* c, const uint32_t* a, uint32_t b0, uint32_t b1) {
    asm volatile(
        "mma.sync.aligned.m16n8k16.row.col.f32.f16.f16.f32 "
        "{%0,%1,%2,%3}, {%4,%5,%6,%7}, {%8,%9}, {%0,%1,%2,%3};"
        : "+f"(c[0]), "+f"(c[1]), "+f"(c[2]), "+f"(c[3])
        : "r"(a[0]), "r"(a[1]), "r"(a[2]), "r"(a[3]), "r"(b0), "r"(b1));
}

// ---------------- kernel 1: weight partial stats ----------------
__global__ void __launch_bounds__(256) wstats1_kernel(const float* __restrict__ w) {
    int t = threadIdx.x;
    int b = blockIdx.x;
    const float* p = w + (size_t)b * 4096;
    double s = 0.0;
    float mx = 0.0f;
#pragma unroll
    for (int i = 0; i < 16; i++) {
        float v = p[t + i * 256];
        s += (double)v;
        mx = fmaxf(mx, fabsf(v));
    }
    __shared__ double ss[256];
    __shared__ float  sx[256];
    ss[t] = s; sx[t] = mx;
    __syncthreads();
    for (int st = 128; st > 0; st >>= 1) {
        if (t < st) { ss[t] += ss[t + st]; sx[t] = fmaxf(sx[t], sx[t + st]); }
        __syncthreads();
    }
    if (t == 0) { g_wsum_part[b] = ss[0]; g_wmax_part[b] = sx[0]; }
}

// ---------------- kernel 2: final stats ----------------
__global__ void __launch_bounds__(256) wstats2_kernel() {
    int t = threadIdx.x;
    __shared__ double ss[256];
    __shared__ float  sx[256];
    ss[t] = g_wsum_part[t];
    sx[t] = g_wmax_part[t];
    __syncthreads();
    for (int st = 128; st > 0; st >>= 1) {
        if (t < st) { ss[t] += ss[t + st]; sx[t] = fmaxf(sx[t], sx[t + st]); }
        __syncthreads();
    }
    if (t == 0) {
        g_a    = (float)(ss[0] / 1048576.0);
        g_beta = sx[0];
    }
}

// ---------------- kernel 3: quantize+transpose weight -> f16 {-1,0,+1} ----------------
__global__ void __launch_bounds__(1024) wquant_kernel(const float* __restrict__ w) {
    __shared__ float tile[32][33];
    int tx = threadIdx.x, ty = threadIdx.y;
    int n0 = blockIdx.x * 32, k0 = blockIdx.y * 32;
    tile[ty][tx] = w[(size_t)(k0 + ty) * NDIM + (n0 + tx)];
    __syncthreads();
    float a = g_a;
    float d = tile[tx][ty] - a;             // w[k0+tx][n0+ty] - a
    float q = (d > 0.0f) ? 1.0f : ((d < 0.0f) ? -1.0f : 0.0f);
    g_wq[(size_t)(n0 + ty) * KDIM + (k0 + tx)] = __float2half_rn(q);
}

// ---------------- kernel 4: per-row gamma + x -> f16 quant ----------------
__global__ void __launch_bounds__(128) xquant_kernel(const float* __restrict__ x) {
    int row = blockIdx.x;
    int t = threadIdx.x, wid = t >> 5, lane = t & 31;
    const float4* xr = (const float4*)(x + (size_t)row * KDIM);
    float4 a = xr[2 * t];
    float4 b = xr[2 * t + 1];
    float m = fabsf(a.x);
    m = fmaxf(m, fabsf(a.y)); m = fmaxf(m, fabsf(a.z)); m = fmaxf(m, fabsf(a.w));
    m = fmaxf(m, fabsf(b.x)); m = fmaxf(m, fabsf(b.y));
    m = fmaxf(m, fabsf(b.z)); m = fmaxf(m, fabsf(b.w));
#pragma unroll
    for (int o = 16; o > 0; o >>= 1) m = fmaxf(m, __shfl_xor_sync(0xffffffffu, m, o));
    __shared__ float sm[4];
    if (lane == 0) sm[wid] = m;
    __syncthreads();
    float gamma = fmaxf(fmaxf(sm[0], sm[1]), fmaxf(sm[2], sm[3]));
    if (t == 0) g_gamma[row] = gamma;
    float inv = 1.0f / (gamma + 1e-5f);
    const float HI = (float)(1.0 - 1e-5);
    __align__(16) __half h[8];
    float v;
    v = a.x * inv; v = fminf(fmaxf(v, -HI), HI); h[0] = __float2half_rn(v);
    v = a.y * inv; v = fminf(fmaxf(v, -HI), HI); h[1] = __float2half_rn(v);
    v = a.z * inv; v = fminf(fmaxf(v, -HI), HI); h[2] = __float2half_rn(v);
    v = a.w * inv; v = fminf(fmaxf(v, -HI), HI); h[3] = __float2half_rn(v);
    v = b.x * inv; v = fminf(fmaxf(v, -HI), HI); h[4] = __float2half_rn(v);
    v = b.y * inv; v = fminf(fmaxf(v, -HI), HI); h[5] = __float2half_rn(v);
    v = b.z * inv; v = fminf(fmaxf(v, -HI), HI); h[6] = __float2half_rn(v);
    v = b.w * inv; v = fminf(fmaxf(v, -HI), HI); h[7] = __float2half_rn(v);
    ((uint4*)(g_xq + (size_t)row * KDIM))[t] = *(const uint4*)h;
}

// ---------------- kernel 5: mma.sync GEMM + scaled epilogue ----------------
// Tile 128(M) x 128(N), K_blk = 64 halves, 3-stage cp.async pipeline.
// 8 warps: 4(M) x 2(N); warp tile 32(M) x 64(N); m16n8k16 HMMA, fp32 accum.

#define BK 64
#define STAGES 3
#define KITERS (KDIM / BK)          // 16
#define STAGE_BYTES 32768           // A 16KB + B 16KB
#define B_OFF 16384
#define GEMM_SMEM_TOTAL (STAGES * STAGE_BYTES)   // 96 KB

DINLINE void load_stage(uint32_t sbase, const __half* __restrict__ Ab,
                        const __half* __restrict__ Bb, int kb) {
    int tid = threadIdx.x;
    const __half* Ak = Ab + kb * BK;
    const __half* Bk = Bb + kb * BK;
#pragma unroll
    for (int i = 0; i < 4; i++) {
        int c = tid + i * 256;          // 0..1023
        int row = c >> 3;               // 0..127
        int col = c & 7;                // 16B chunk
        uint32_t off = (uint32_t)(row * 128 + col * 16);
        uint32_t sw = sw128(off);
        cpa16(sbase + sw,         (const void*)(Ak + (size_t)row * KDIM + col * 8));
        cpa16(sbase + B_OFF + sw, (const void*)(Bk + (size_t)row * KDIM + col * 8));
    }
}

__global__ void __launch_bounds__(256) gemm_kernel(float* __restrict__ out) {
    extern __shared__ char smem[];
    uint32_t sb = s2u(smem);
    int tid = threadIdx.x, wid = tid >> 5, lane = tid & 31;
    int wm = wid & 3;       // 0..3 -> M offset wm*32
    int wn = wid >> 2;      // 0..1 -> N offset wn*64
    int n0 = blockIdx.x * 128;
    int m0 = blockIdx.y * 128;

    const __half* A = g_xq + (size_t)m0 * KDIM;
    const __half* B = g_wq + (size_t)n0 * KDIM;

    float acc[2][8][4];
#pragma unroll
    for (int i = 0; i < 2; i++)
#pragma unroll
        for (int j = 0; j < 8; j++)
#pragma unroll
            for (int k = 0; k < 4; k++) acc[i][j][k] = 0.0f;

    load_stage(sb, A, B, 0);
    asm volatile("cp.async.commit_group;");
    load_stage(sb + STAGE_BYTES, A, B, 1);
    asm volatile("cp.async.commit_group;");

    int lrow = lane & 15;           // row within 16x16 tile
    int lkh  = (lane >> 4) * 8;     // k-half select

#pragma unroll 1
    for (int kb = 0; kb < KITERS; kb++) {
        if (kb == KITERS - 1) asm volatile("cp.async.wait_group 0;" ::: "memory");
        else                  asm volatile("cp.async.wait_group 1;" ::: "memory");
        __syncthreads();
        if (kb + 2 < KITERS) {
            load_stage(sb + ((kb + 2) % STAGES) * STAGE_BYTES, A, B, kb + 2);
            asm volatile("cp.async.commit_group;");
        }
        uint32_t st = sb + (kb % STAGES) * STAGE_BYTES;
#pragma unroll
        for (int ks = 0; ks < 4; ks++) {
            int k0 = ks * 16;
            uint32_t a[2][4];
#pragma unroll
            for (int mt = 0; mt < 2; mt++) {
                int r = wm * 32 + mt * 16 + lrow;
                uint32_t addr = st + sw128((uint32_t)(r * 128 + (k0 + lkh) * 2));
                ldsm_x4(addr, a[mt][0], a[mt][1], a[mt][2], a[mt][3]);
            }
            uint32_t b[4][4];
#pragma unroll
            for (int g = 0; g < 4; g++) {
                int n = wn * 64 + g * 16 + lrow;
                uint32_t addr = st + B_OFF + sw128((uint32_t)(n * 128 + (k0 + lkh) * 2));
                ldsm_x4(addr, b[g][0], b[g][1], b[g][2], b[g][3]);
            }
#pragma unroll
            for (int mt = 0; mt < 2; mt++)
#pragma unroll
                for (int g = 0; g < 4; g++) {
                    mma16816(acc[mt][2 * g],     a[mt], b[g][0], b[g][2]);
                    mma16816(acc[mt][2 * g + 1], a[mt], b[g][1], b[g][3]);
                }
        }
    }

    // ---------------- epilogue: scale by beta*gamma[row], direct STG ----------------
    float beta = g_beta;
    int gr = lane >> 2;             // 0..7
    int c2 = (lane & 3) * 2;
#pragma unroll
    for (int mt = 0; mt < 2; mt++) {
        int r0 = m0 + wm * 32 + mt * 16 + gr;
        int r1 = r0 + 8;
        float s0 = beta * g_gamma[r0];
        float s1 = beta * g_gamma[r1];
        float* o0 = out + (size_t)r0 * NDIM + n0 + wn * 64 + c2;
        float* o1 = out + (size_t)r1 * NDIM + n0 + wn * 64 + c2;
#pragma unroll
        for (int nt = 0; nt < 8; nt++) {
            float2 v0 = make_float2(acc[mt][nt][0] * s0, acc[mt][nt][1] * s0);
            float2 v1 = make_float2(acc[mt][nt][2] * s1, acc[mt][nt][3] * s1);
            *(float2*)(o0 + nt * 8) = v0;
            *(float2*)(o1 + nt * 8) = v1;
        }
    }
}

// ---------------- launch ----------------
extern "C" void kernel_launch(void* const* d_in, const int* in_sizes, int n_in,
                              void* d_out, int out_size) {
    const float* x = (const float*)d_in[0];
    const float* w = (const float*)d_in[1];
    float* out = (float*)d_out;

    wstats1_kernel<<<256, 256>>>(w);
    wstats2_kernel<<<1, 256>>>();
    wquant_kernel<<<dim3(32, 32), dim3(32, 32)>>>(w);
    xquant_kernel<<<MDIM, 128>>>(x);

    cudaFuncSetAttribute(gemm_kernel, cudaFuncAttributeMaxDynamicSharedMemorySize,
                         GEMM_SMEM_TOTAL);
    gemm_kernel<<<dim3(NDIM / 128, MDIM / 128), 256, GEMM_SMEM_TOTAL>>>(out);
}